// round 4
// baseline (speedup 1.0000x reference)
#include <cuda_runtime.h>
#include <cuda_bf16.h>

// GADBase: guided anisotropic diffusion.
//   inputs:  guide [2,3,1024,1024] f32, y_bicubic [2,1,1024,1024] f32,
//            source [2,1,128,128] f32, mask_lr [2,1,128,128] f32
//   outputs: y_pred [2,1,1024,1024], cv [2,1,1023,1024], ch [2,1,1024,1023]
//            concatenated flat in that order.
//
// Structure:
//   k_min_init : min(source) -> shift (device scalar), ratioA := 1
//   k_prep     : imA = y + shift ; cv/ch from [guide, img] diffs (shift cancels
//                in the img diff). cv/ch written to d_out AND to zero-padded
//                [1024x1024] scratch (g_cvp row 1023 = 0, g_chp col 1023 = 0).
//   k_step x64 : 5-point stencil (reads im_in * ratio_in on SMEM fill),
//                per-8x8-block sums via shfl, writes ratio_out. Double-buffered
//                im and ratio.
//   k_epi      : y_pred = im * ratio - shift.

#define HH 1024
#define WW 1024
#define NPIX (HH*WW)          // 1048576 per batch
#define NBLK (128*128)        // 16384 lr pixels per batch
#define CV_OFF 2097152
#define CH_OFF 4192256        // 2097152 + 2*1023*1024

__device__ float g_imA[2*NPIX];
__device__ float g_imB[2*NPIX];
__device__ float g_cvp[2*NPIX];   // padded cv (row 1023 = 0)
__device__ float g_chp[2*NPIX];   // padded ch (col 1023 = 0)
__device__ float g_ratA[2*NBLK];
__device__ float g_ratB[2*NBLK];
__device__ float g_shift;

// ---------------------------------------------------------------------------
__global__ void k_min_init(const float* __restrict__ src)
{
    __shared__ float red[32];
    int tid = threadIdx.x;                     // 1024 threads
    float mn = 1e30f;
    for (int i = tid; i < 2*NBLK; i += 1024) mn = fminf(mn, src[i]);
    #pragma unroll
    for (int o = 16; o; o >>= 1) mn = fminf(mn, __shfl_xor_sync(~0u, mn, o));
    if ((tid & 31) == 0) red[tid >> 5] = mn;
    __syncthreads();
    if (tid < 32) {
        float v = red[tid];
        #pragma unroll
        for (int o = 16; o; o >>= 1) v = fminf(v, __shfl_xor_sync(~0u, v, o));
        if (tid == 0) g_shift = (v <= 0.1f) ? 0.1f : 0.0f;
    }
    for (int i = tid; i < 2*NBLK; i += 1024) g_ratA[i] = 1.0f;
}

// ---------------------------------------------------------------------------
__global__ void k_prep(const float* __restrict__ guide,
                       const float* __restrict__ y,
                       float* __restrict__ out)
{
    int c = blockIdx.x*32 + threadIdx.x;
    int r = blockIdx.y*8  + threadIdx.y;
    int b = blockIdx.z;
    const float shift = g_shift;
    const float K2 = (float)(0.03*0.03);       // 9e-4 (double, then f32)

    int p  = b*NPIX + r*1024 + c;
    int gb = b*3*NPIX + r*1024 + c;
    float yc = y[p];
    g_imA[p] = yc + shift;

    float cvv = 0.f;
    if (r < 1023) {
        float s = fabsf(guide[gb          + 1024] - guide[gb]);
        s      += fabsf(guide[gb +   NPIX + 1024] - guide[gb +   NPIX]);
        s      += fabsf(guide[gb + 2*NPIX + 1024] - guide[gb + 2*NPIX]);
        s      += fabsf(y[p + 1024] - yc);      // shift cancels in diff
        s *= 0.25f;
        cvv = 1.0f / (1.0f + s*s / K2);
        out[CV_OFF + b*(1023*1024) + r*1024 + c] = cvv;
    }
    g_cvp[p] = cvv;

    float chh = 0.f;
    if (c < 1023) {
        float s = fabsf(guide[gb          + 1] - guide[gb]);
        s      += fabsf(guide[gb +   NPIX + 1] - guide[gb +   NPIX]);
        s      += fabsf(guide[gb + 2*NPIX + 1] - guide[gb + 2*NPIX]);
        s      += fabsf(y[p + 1] - yc);
        s *= 0.25f;
        chh = 1.0f / (1.0f + s*s / K2);
        out[CH_OFF + b*(1024*1023) + r*1023 + c] = chh;
    }
    g_chp[p] = chh;
}

// ---------------------------------------------------------------------------
// One diffusion iteration. Tile 128 wide x 16 tall, 256 threads, 8 rows/thread.
// SMEM holds the ratio-scaled image tile + 1-pixel halo.
#define SSTR 132
__global__ __launch_bounds__(256)
void k_step(int t, const float* __restrict__ src, const float* __restrict__ mask)
{
    const float* __restrict__ im_in  = (t & 1) ? g_imB  : g_imA;
    float*       __restrict__ im_out = (t & 1) ? g_imA  : g_imB;
    const float* __restrict__ rin    = (t & 1) ? g_ratB : g_ratA;
    float*       __restrict__ rout   = (t & 1) ? g_ratA : g_ratB;

    __shared__ float s_im[18*SSTR];

    int tid = threadIdx.x;
    int b   = blockIdx.z;
    int colbase = blockIdx.x * 128;
    int rowbase = blockIdx.y * 16;
    int pbase = b * NPIX;
    int rbase = b * NBLK;

    // fill 18x130 halo tile, applying previous-iteration ratio per source block
    for (int idx = tid; idx < 18*130; idx += 256) {
        int lr = idx / 130, lc = idx - lr*130;
        int gr = rowbase - 1 + lr, gc = colbase - 1 + lc;
        float v = 0.f;
        if ((unsigned)gr < 1024u && (unsigned)gc < 1024u)
            v = im_in[pbase + gr*1024 + gc] * rin[rbase + (gr>>3)*128 + (gc>>3)];
        s_im[lr*SSTR + lc] = v;
    }
    __syncthreads();

    int tx = tid & 127, ty = tid >> 7;
    int c  = colbase + tx;
    int r0 = rowbase + ty*8;
    int lc = tx + 1;

    float up  = s_im[(ty*8    )*SSTR + lc];
    float cen = s_im[(ty*8 + 1)*SSTR + lc];
    float cvu = (r0 > 0) ? g_cvp[pbase + (r0-1)*1024 + c] : 0.f;
    bool hasl = (c > 0);
    float acc = 0.f;
    int p = pbase + r0*1024 + c;

    #pragma unroll
    for (int i = 0; i < 8; i++) {
        int lr = ty*8 + i + 1;
        float dn = s_im[(lr+1)*SSTR + lc];
        float lf = s_im[lr*SSTR + lc - 1];
        float rt = s_im[lr*SSTR + lc + 1];
        float cvd  = g_cvp[p];               // row 1023 is zero-padded
        float chl  = hasl ? g_chp[p-1] : 0.f;
        float chr_ = g_chp[p];               // col 1023 is zero-padded
        float o = cen + 0.24f * ( cvd *(dn - cen) - cvu*(cen - up)
                                + chr_*(rt - cen) - chl*(cen - lf) );
        im_out[p] = o;
        acc += o;
        up = cen; cen = dn; cvu = cvd;
        p += 1024;
    }

    // per-8x8-block sum: each thread's acc covers 8 rows of one column; sum
    // across the 8 lanes sharing a block column (lanes are consecutive tx).
    acc += __shfl_xor_sync(~0u, acc, 1);
    acc += __shfl_xor_sync(~0u, acc, 2);
    acc += __shfl_xor_sync(~0u, acc, 4);
    if ((tx & 7) == 0) {
        int bi = rbase + (r0 >> 3)*128 + (c >> 3);
        float mean = acc * (1.0f/64.0f);
        float ratio = (mask[bi] < 0.5f) ? 1.0f
                                        : (src[bi] + g_shift) / (mean + 1e-8f);
        rout[bi] = ratio;
    }
}

// ---------------------------------------------------------------------------
__global__ void k_epi(float* __restrict__ out)
{
    int idx = blockIdx.x*256 + threadIdx.x;   // 2*NPIX total
    int b  = idx >> 20;
    int rc = idx & (NPIX - 1);
    int r = rc >> 10, c = rc & 1023;
    out[idx] = g_imA[idx] * g_ratA[b*NBLK + (r>>3)*128 + (c>>3)] - g_shift;
}

// ---------------------------------------------------------------------------
extern "C" void kernel_launch(void* const* d_in, const int* in_sizes, int n_in,
                              void* d_out, int out_size)
{
    const float* guide = (const float*)d_in[0];
    const float* y     = (const float*)d_in[1];
    const float* src   = (const float*)d_in[2];
    const float* mask  = (const float*)d_in[3];
    float* out = (float*)d_out;

    k_min_init<<<1, 1024>>>(src);

    dim3 bp(32, 8), gp(1024/32, 1024/8, 2);
    k_prep<<<gp, bp>>>(guide, y, out);

    dim3 gs(1024/128, 1024/16, 2);          // 8 x 64 x 2 = 1024 CTAs
    for (int t = 0; t < 64; t++)
        k_step<<<gs, 256>>>(t, src, mask);

    k_epi<<<(2*NPIX)/256, 256>>>(out);
}

// round 8
// speedup vs baseline: 2.2688x; 2.2688x over previous
#include <cuda_runtime.h>

// GADBase guided anisotropic diffusion — single persistent kernel.
// Each CTA owns a 128x32 tile (512 CTAs total, all co-resident at 4/SM).
// Image tile + L-prescaled conductances live in SMEM for all 64 iterations;
// only 1-px boundary rings are exchanged via L2 with per-neighbor flag sync.

#define NPIX   (1024*1024)
#define CV_OFF 2097152
#define CH_OFF 4192256
#define TW 128
#define TH 32
#define GX 8
#define GY 32
#define NCTA (2*GX*GY)        // 512

#define IMS   136             // s_im row stride (halo at idx 3 / 132, interior 4..131)
#define CST   132             // s_c row stride
#define OFF_A 4624            // 34*136
#define OFF_C 8848            // + 33*128
#define OFF_P 13072           // + 32*132
#define OFF_R 13200
#define OFF_S 13264
#define OFF_M 13328
#define SMEMF 13392           // floats -> 53568 bytes

__device__ float g_shift;
__device__ int   g_flag[NCTA];
__device__ float g_brow[2][2][GY][2][1024];   // [parity][batch][ty][top/bot][col]
__device__ float g_bcol[2][2][GX][2][1024];   // [parity][batch][bx][left/right][row]

// ---------------------------------------------------------------------------
__global__ void k_pre(const float* __restrict__ src)
{
    __shared__ float red[32];
    int tid = threadIdx.x;                       // 1024 threads
    float mn = 1e30f;
    for (int i = tid; i < 2*128*128; i += 1024) mn = fminf(mn, src[i]);
    #pragma unroll
    for (int o = 16; o; o >>= 1) mn = fminf(mn, __shfl_xor_sync(~0u, mn, o));
    if ((tid & 31) == 0) red[tid >> 5] = mn;
    __syncthreads();
    if (tid < 32) {
        float v = red[tid];
        #pragma unroll
        for (int o = 16; o; o >>= 1) v = fminf(v, __shfl_xor_sync(~0u, v, o));
        if (tid == 0) g_shift = (v <= 0.1f) ? 0.1f : 0.0f;
    }
    if (tid < NCTA) g_flag[tid] = 0;
}

// ---------------------------------------------------------------------------
extern __shared__ float sm[];

__global__ void __launch_bounds__(256, 4)
k_diffuse(const float* __restrict__ guide, const float* __restrict__ y,
          const float* __restrict__ src,   const float* __restrict__ mask,
          float* __restrict__ out)
{
    int tid = threadIdx.x;
    int bx = blockIdx.x, ty = blockIdx.y, bz = blockIdx.z;
    int colbase = bx * TW, rowbase = ty * TH;
    int pb = bz * NPIX;
    float shift = g_shift;
    const float K2 = 0.03f * 0.03f;

    // ---- s_im: 34x136 with halo (state 0 = y + shift everywhere) ----
    for (int i = tid; i < 34*IMS; i += 256) {
        int r = i / IMS, c = i - r*IMS;
        int gr = rowbase + r - 1, gc = colbase + c - 4;
        float v = 0.f;
        if ((unsigned)gr < 1024u && (unsigned)gc < 1024u)
            v = y[pb + gr*1024 + gc] + shift;
        sm[i] = v;
    }
    // ---- s_a = 0.24*cv, rows rowbase-1..rowbase+31 (33x128) ----
    const float* g0 = guide + bz*3*NPIX;
    for (int i = tid; i < 33*128; i += 256) {
        int r = i >> 7, c = i & 127;
        int gr = rowbase + r - 1, gc = colbase + c;
        float a = 0.f;
        if ((unsigned)gr < 1023u) {
            int q = gr*1024 + gc;
            float s = fabsf(g0[q+1024]        - g0[q]);
            s      += fabsf(g0[q+NPIX+1024]   - g0[q+NPIX]);
            s      += fabsf(g0[q+2*NPIX+1024] - g0[q+2*NPIX]);
            s      += fabsf(y[pb+q+1024]      - y[pb+q]);      // shift cancels
            s *= 0.25f;
            float cvv = 1.0f / (1.0f + s*s / K2);
            if (gr >= rowbase)
                out[CV_OFF + bz*(1023*1024) + q] = cvv;
            a = 0.24f * cvv;
        }
        sm[OFF_A + i] = a;
    }
    // ---- s_c = 0.24*ch, rows rowbase..+31, cols colbase-1..colbase+127 ----
    for (int i = tid; i < 32*129; i += 256) {
        int r = i / 129, c = i - r*129 - 1;     // c in [-1,127]
        int gr = rowbase + r, gc = colbase + c;
        float a = 0.f;
        if ((unsigned)gc < 1023u) {
            int q = gr*1024 + gc;
            float s = fabsf(g0[q+1]        - g0[q]);
            s      += fabsf(g0[q+NPIX+1]   - g0[q+NPIX]);
            s      += fabsf(g0[q+2*NPIX+1] - g0[q+2*NPIX]);
            s      += fabsf(y[pb+q+1]      - y[pb+q]);
            s *= 0.25f;
            float chh = 1.0f / (1.0f + s*s / K2);
            if (gc >= colbase)
                out[CH_OFF + bz*(1024*1023) + gr*1023 + gc] = chh;
            a = 0.24f * chh;
        }
        sm[OFF_C + r*CST + 4 + c] = a;
    }
    // ---- per-block source/mask (64 blocks: 4 rows x 16 cols) ----
    if (tid < 64) {
        int br = tid >> 4, bc = tid & 15;
        int bi = bz*16384 + ((rowbase>>3) + br)*128 + (colbase>>3) + bc;
        sm[OFF_S + tid] = src[bi] + shift;
        sm[OFF_M + tid] = (mask[bi] < 0.5f) ? 0.f : 1.f;
    }
    __syncthreads();

    int cg = tid & 31, rg = tid >> 5;
    int c0 = cg * 4, r0 = rg * 4;               // 4x4 px per thread
    int base_im = (r0 + 1)*IMS + 4 + c0;
    int cid = (bz*GY + ty)*GX + bx;

    for (int t = 0; t < 64; t++) {
        float4 up  = *(float4*)&sm[base_im - IMS];
        float4 cen = *(float4*)&sm[base_im];
        float4 au  = *(float4*)&sm[OFF_A + r0*128 + c0];
        float4 o[4];
        float acc = 0.f;
        #pragma unroll
        for (int i = 0; i < 4; i++) {
            float4 dn = *(float4*)&sm[base_im + (i+1)*IMS];
            float4 ad = *(float4*)&sm[OFF_A + (r0+1+i)*128 + c0];
            float4 cr = *(float4*)&sm[OFF_C + (r0+i)*CST + 4 + c0];
            float cl0 = sm[OFF_C + (r0+i)*CST + 3 + c0];
            float lf0 = sm[base_im + i*IMS - 1];
            float rt3 = sm[base_im + i*IMS + 4];
            float ox = cen.x + (ad.x*(dn.x-cen.x) - au.x*(cen.x-up.x) + cr.x*(cen.y-cen.x) - cl0 *(cen.x-lf0 ));
            float oy = cen.y + (ad.y*(dn.y-cen.y) - au.y*(cen.y-up.y) + cr.y*(cen.z-cen.y) - cr.x*(cen.y-cen.x));
            float oz = cen.z + (ad.z*(dn.z-cen.z) - au.z*(cen.z-up.z) + cr.z*(cen.w-cen.z) - cr.y*(cen.z-cen.y));
            float ow = cen.w + (ad.w*(dn.w-cen.w) - au.w*(cen.w-up.w) + cr.w*(rt3  -cen.w) - cr.z*(cen.w-cen.z));
            o[i] = make_float4(ox, oy, oz, ow);
            acc += (ox + oy) + (oz + ow);
            up = cen; cen = dn; au = ad;
        }
        // 8x8 block sums: pair columns via shfl, pair row-groups via smem
        acc += __shfl_xor_sync(0xffffffffu, acc, 1);
        if (!(tid & 1)) sm[OFF_P + rg*16 + (cg >> 1)] = acc;
        __syncthreads();
        if (tid < 64) {
            int br = tid >> 4, bc = tid & 15;
            float ssum = sm[OFF_P + (2*br)*16 + bc] + sm[OFF_P + (2*br+1)*16 + bc];
            float mean = ssum * (1.f/64.f);
            float ratio = (sm[OFF_M + tid] != 0.f) ? sm[OFF_S + tid] / (mean + 1e-8f)
                                                   : 1.0f;
            sm[OFF_R + tid] = ratio;
        }
        __syncthreads();
        float ratio = sm[OFF_R + (r0 >> 3)*16 + (c0 >> 3)];
        #pragma unroll
        for (int i = 0; i < 4; i++) {
            o[i].x *= ratio; o[i].y *= ratio; o[i].z *= ratio; o[i].w *= ratio;
        }

        if (t == 63) {
            #pragma unroll
            for (int i = 0; i < 4; i++) {
                float4 v = make_float4(o[i].x - shift, o[i].y - shift,
                                       o[i].z - shift, o[i].w - shift);
                *(float4*)&out[pb + (rowbase + r0 + i)*1024 + colbase + c0] = v;
            }
        } else {
            #pragma unroll
            for (int i = 0; i < 4; i++)
                *(float4*)&sm[base_im + i*IMS] = o[i];
            int par = (t + 1) & 1;
            if (r0 == 0) {
                float* d = &g_brow[par][bz][ty][0][colbase + c0];
                __stcg(d+0, o[0].x); __stcg(d+1, o[0].y);
                __stcg(d+2, o[0].z); __stcg(d+3, o[0].w);
            }
            if (r0 == TH - 4) {
                float* d = &g_brow[par][bz][ty][1][colbase + c0];
                __stcg(d+0, o[3].x); __stcg(d+1, o[3].y);
                __stcg(d+2, o[3].z); __stcg(d+3, o[3].w);
            }
            if (c0 == 0) {
                float* d = &g_bcol[par][bz][bx][0][rowbase + r0];
                __stcg(d+0, o[0].x); __stcg(d+1, o[1].x);
                __stcg(d+2, o[2].x); __stcg(d+3, o[3].x);
            }
            if (c0 == TW - 4) {
                float* d = &g_bcol[par][bz][bx][1][rowbase + r0];
                __stcg(d+0, o[0].w); __stcg(d+1, o[1].w);
                __stcg(d+2, o[2].w); __stcg(d+3, o[3].w);
            }
            __threadfence();
            __syncthreads();
            if (tid == 0) atomicExch(&g_flag[cid], t + 1);
            if (tid < 4) {                       // wait the 4 neighbors
                int nid = -1;
                if (tid == 0 && ty > 0)      nid = cid - GX;
                if (tid == 1 && ty < GY - 1) nid = cid + GX;
                if (tid == 2 && bx > 0)      nid = cid - 1;
                if (tid == 3 && bx < GX - 1) nid = cid + 1;
                if (nid >= 0)
                    while (((volatile int*)g_flag)[nid] < t + 1) { }
            }
            __syncthreads();
            // halo refill from neighbors' published rings (L2, bypass L1)
            if (tid < 128) {
                if (ty > 0)
                    sm[4 + tid] = __ldcg(&g_brow[par][bz][ty-1][1][colbase + tid]);
            } else {
                int c = tid - 128;
                if (ty < GY - 1)
                    sm[33*IMS + 4 + c] = __ldcg(&g_brow[par][bz][ty+1][0][colbase + c]);
            }
            if (tid < 32) {
                if (bx > 0)
                    sm[(1 + tid)*IMS + 3] = __ldcg(&g_bcol[par][bz][bx-1][1][rowbase + tid]);
            } else if (tid < 64) {
                int r = tid - 32;
                if (bx < GX - 1)
                    sm[(1 + r)*IMS + 132] = __ldcg(&g_bcol[par][bz][bx+1][0][rowbase + r]);
            }
            __syncthreads();
        }
    }
}

// ---------------------------------------------------------------------------
extern "C" void kernel_launch(void* const* d_in, const int* in_sizes, int n_in,
                              void* d_out, int out_size)
{
    const float* guide = (const float*)d_in[0];
    const float* y     = (const float*)d_in[1];
    const float* src   = (const float*)d_in[2];
    const float* mask  = (const float*)d_in[3];
    float* out = (float*)d_out;

    cudaFuncSetAttribute(k_diffuse, cudaFuncAttributeMaxDynamicSharedMemorySize,
                         SMEMF * sizeof(float));

    k_pre<<<1, 1024>>>(src);
    dim3 g(GX, GY, 2);                           // 512 CTAs, all co-resident
    k_diffuse<<<g, 256, SMEMF * sizeof(float)>>>(guide, y, src, mask, out);
}